// round 2
// baseline (speedup 1.0000x reference)
#include <cuda_runtime.h>
#include <math.h>

// Problem constants
#define Bb   2
#define T    2048
#define D    1024
#define H    16
#define HS   64
#define NT   (Bb * T)      // 4096 tokens
#define DFF  (4 * D)       // 4096
#define QKVW (3 * D)       // 3072 fused QKV width
#define LNEPS 1e-5f

// ---------------- Scratch (static device globals; no allocation) ----------------
__device__ float g_x   [(long)NT * D];     // LN1 output
__device__ float g_wqkv[(long)D * QKVW];   // packed [D, 3072] QKV weights
__device__ float g_qkv [(long)NT * QKVW];  // fused QKV [token][3072]
__device__ float g_attn[(long)NT * D];     // attention output (concat heads)
__device__ float g_x2  [(long)NT * D];     // embds + attn (residual stream)
__device__ float g_y   [(long)NT * D];     // LN2 output
__device__ float g_h   [(long)NT * DFF];   // FFN hidden

// ---------------- Pack Wq/Wk/Wv [H,D,HS] -> [D, 3*H*HS] ----------------
__global__ __launch_bounds__(256)
void pack_qkv(const float* __restrict__ Wq, const float* __restrict__ Wk,
              const float* __restrict__ Wv, float* __restrict__ wp)
{
    int idx = blockIdx.x * 256 + threadIdx.x;     // over D*H*HS = 1M
    int k = idx >> 10;                            // 0..1023
    int r = idx & 1023;                           // h*HS + e
    int h = r >> 6, e = r & 63;
    long src = (long)h * D * HS + (long)k * HS + e;
    long dst = (long)k * QKVW + r;
    wp[dst]            = Wq[src];
    wp[dst + D]        = Wk[src];
    wp[dst + 2 * D]    = Wv[src];
}

// ---------------- LayerNorm (optionally fused residual-add) ----------------
__global__ __launch_bounds__(256)
void ln_kernel(const float* __restrict__ x, const float* __restrict__ res,
               const float* __restrict__ gw, const float* __restrict__ bw,
               float* __restrict__ y, float* __restrict__ xout)
{
    int row = blockIdx.x;
    int tid = threadIdx.x;
    const float* xr = x + (long)row * D;

    float v[4];
#pragma unroll
    for (int i = 0; i < 4; i++) v[i] = xr[tid + i * 256];

    if (res) {
        const float* rr = res + (long)row * D;
#pragma unroll
        for (int i = 0; i < 4; i++) v[i] += rr[tid + i * 256];
    }
    if (xout) {
        float* xo = xout + (long)row * D;
#pragma unroll
        for (int i = 0; i < 4; i++) xo[tid + i * 256] = v[i];
    }

    __shared__ float red[256];

    float s = (v[0] + v[1]) + (v[2] + v[3]);
    red[tid] = s;
    __syncthreads();
#pragma unroll
    for (int off = 128; off > 0; off >>= 1) {
        if (tid < off) red[tid] += red[tid + off];
        __syncthreads();
    }
    float mean = red[0] * (1.0f / D);
    __syncthreads();

    float sq = 0.f;
#pragma unroll
    for (int i = 0; i < 4; i++) { float dv = v[i] - mean; sq = fmaf(dv, dv, sq); }
    red[tid] = sq;
    __syncthreads();
#pragma unroll
    for (int off = 128; off > 0; off >>= 1) {
        if (tid < off) red[tid] += red[tid + off];
        __syncthreads();
    }
    float var = red[0] * (1.0f / D);
    float inv = rsqrtf(var + LNEPS);

    float* yr = y + (long)row * D;
#pragma unroll
    for (int i = 0; i < 4; i++) {
        int c = tid + i * 256;
        yr[c] = (v[i] - mean) * inv * gw[c] + bw[c];
    }
}

// ---------------- 128x128x8 double-buffered fp32 SGEMM ----------------
// C[m][n] = sum_k A[m][k]*B[k][n]  (+bias[n]) (relu) (+Rs[m][n])
// 256 threads, 8x8 microtile per thread (split 4+4 with 64 offset).
// Requires M%128==0, N%128==0, K%8==0, 16B-aligned rows.
template<bool RELU, bool HAS_BIAS, bool HAS_RES>
__global__ __launch_bounds__(256)
void sgemm128(const float* __restrict__ A, const float* __restrict__ Bm,
              const float* __restrict__ bias, const float* __restrict__ Rs,
              float* __restrict__ C,
              int M, int N, int K, int lda, int ldb, int ldc)
{
    __shared__ float As[2][8][132];   // [buf][k][m], padded
    __shared__ float Bs[2][8][128];   // [buf][k][n]

    int tid  = threadIdx.x;
    int row0 = blockIdx.x * 128;
    int col0 = blockIdx.y * 128;

    // Load mappings (one float4 per thread per tile per matrix)
    int arow = tid >> 1;              // 0..127
    int ak   = (tid & 1) * 4;         // 0 or 4
    int bk   = tid >> 5;              // 0..7
    int bn   = (tid & 31) * 4;        // 0..124

    const float* Aptr = A + (long)(row0 + arow) * lda + ak;
    const float* Bptr = Bm + (long)bk * ldb + col0 + bn;

    int tx = tid & 15, ty = tid >> 4;

    float acc[8][8];
#pragma unroll
    for (int i = 0; i < 8; i++)
#pragma unroll
        for (int j = 0; j < 8; j++) acc[i][j] = 0.f;

    // Prologue: load tile 0 into buffer 0
    {
        float4 a4 = *(const float4*)Aptr;
        As[0][ak + 0][arow] = a4.x;
        As[0][ak + 1][arow] = a4.y;
        As[0][ak + 2][arow] = a4.z;
        As[0][ak + 3][arow] = a4.w;
        *(float4*)&Bs[0][bk][bn] = *(const float4*)Bptr;
    }
    __syncthreads();

    int nk = K >> 3;
    for (int t = 0; t < nk; t++) {
        int cur = t & 1, nxt = cur ^ 1;
        if (t + 1 < nk) {
            float4 a4 = *(const float4*)(Aptr + (t + 1) * 8);
            float4 b4 = *(const float4*)(Bptr + (long)(t + 1) * 8 * ldb);
            As[nxt][ak + 0][arow] = a4.x;
            As[nxt][ak + 1][arow] = a4.y;
            As[nxt][ak + 2][arow] = a4.z;
            As[nxt][ak + 3][arow] = a4.w;
            *(float4*)&Bs[nxt][bk][bn] = b4;
        }
#pragma unroll
        for (int k = 0; k < 8; k++) {
            float a[8], b[8];
            *(float4*)&a[0] = *(const float4*)&As[cur][k][ty * 4];
            *(float4*)&a[4] = *(const float4*)&As[cur][k][64 + ty * 4];
            *(float4*)&b[0] = *(const float4*)&Bs[cur][k][tx * 4];
            *(float4*)&b[4] = *(const float4*)&Bs[cur][k][64 + tx * 4];
#pragma unroll
            for (int i = 0; i < 8; i++)
#pragma unroll
                for (int j = 0; j < 8; j++)
                    acc[i][j] = fmaf(a[i], b[j], acc[i][j]);
        }
        __syncthreads();
    }

    // Epilogue: 8 rows x 2 col-groups of float4
#pragma unroll
    for (int ih = 0; ih < 2; ih++) {
#pragma unroll
        for (int i = 0; i < 4; i++) {
            int m = row0 + ih * 64 + ty * 4 + i;
            int ai = ih * 4 + i;
#pragma unroll
            for (int jh = 0; jh < 2; jh++) {
                int n = col0 + jh * 64 + tx * 4;
                float4 val;
                val.x = acc[ai][jh * 4 + 0];
                val.y = acc[ai][jh * 4 + 1];
                val.z = acc[ai][jh * 4 + 2];
                val.w = acc[ai][jh * 4 + 3];
                if (HAS_BIAS) {
                    const float4 b4 = *(const float4*)&bias[n];
                    val.x += b4.x; val.y += b4.y; val.z += b4.z; val.w += b4.w;
                }
                if (RELU) {
                    val.x = fmaxf(val.x, 0.f); val.y = fmaxf(val.y, 0.f);
                    val.z = fmaxf(val.z, 0.f); val.w = fmaxf(val.w, 0.f);
                }
                if (HAS_RES) {
                    const float4 r4 = *(const float4*)&Rs[(long)m * ldc + n];
                    val.x += r4.x; val.y += r4.y; val.z += r4.z; val.w += r4.w;
                }
                *(float4*)&C[(long)m * ldc + n] = val;
            }
        }
    }
}

// ---------------- Causal flash attention (fp32, register-resident) ----------------
// qkv layout: [token][3072], token = b*T + t; q at col h*64, k at 1024+h*64, v at 2048+h*64.
// o layout: [token][h*64+e], row stride D.
__global__ __launch_bounds__(128)
void attn_kernel(const float* __restrict__ qkv, float* __restrict__ o)
{
    __shared__ float ksh[64][64];
    __shared__ float vsh[64][64];

    int b  = blockIdx.y / H;
    int h  = blockIdx.y % H;
    int q0 = blockIdx.x * 128;
    int tid = threadIdx.x;
    int qi = q0 + tid;                       // query row within (b,h)

    long qbase = ((long)b * T) * QKVW + (long)h * HS;
    long kbase = qbase + D;
    long vbase = qbase + 2 * D;

    float qr[64];
    const float* qrow = qkv + qbase + (long)qi * QKVW;
#pragma unroll
    for (int d = 0; d < 64; d += 4) {
        float4 v4 = *(const float4*)&qrow[d];
        qr[d + 0] = v4.x; qr[d + 1] = v4.y; qr[d + 2] = v4.z; qr[d + 3] = v4.w;
    }

    float acc[64];
#pragma unroll
    for (int d = 0; d < 64; d++) acc[d] = 0.f;
    float m = -INFINITY, l = 0.f;
    const float scale = 0.03125f;            // D^-0.5 = 1/32 (note: D, not HS)

    int ntiles = (q0 + 128) / 64;            // causal: tiles up to q0+127
    for (int t0 = 0; t0 < ntiles; t0++) {
        int k0 = t0 * 64;
        __syncthreads();
        for (int idx = tid; idx < 64 * 16; idx += 128) {
            int r = idx >> 4, c4 = (idx & 15) * 4;
            *(float4*)&ksh[r][c4] = *(const float4*)&qkv[kbase + (long)(k0 + r) * QKVW + c4];
            *(float4*)&vsh[r][c4] = *(const float4*)&qkv[vbase + (long)(k0 + r) * QKVW + c4];
        }
        __syncthreads();

        int jend = qi - k0 + 1;              // causal mask within tile
        if (jend > 64) jend = 64;
        for (int j = 0; j < jend; j++) {
            float s0 = 0.f, s1 = 0.f, s2 = 0.f, s3 = 0.f;
#pragma unroll
            for (int d = 0; d < 64; d += 4) {
                s0 = fmaf(qr[d + 0], ksh[j][d + 0], s0);
                s1 = fmaf(qr[d + 1], ksh[j][d + 1], s1);
                s2 = fmaf(qr[d + 2], ksh[j][d + 2], s2);
                s3 = fmaf(qr[d + 3], ksh[j][d + 3], s3);
            }
            float s = ((s0 + s1) + (s2 + s3)) * scale;
            if (s > m) {                     // infrequent after warmup
                float corr = __expf(m - s);  // 0 on first key (m = -inf)
                l *= corr;
#pragma unroll
                for (int d = 0; d < 64; d++) acc[d] *= corr;
                m = s;
            }
            float p = __expf(s - m);
            l += p;
#pragma unroll
            for (int d = 0; d < 64; d++)
                acc[d] = fmaf(p, vsh[j][d], acc[d]);
        }
    }

    float invl = 1.f / l;
    long obase = ((long)b * T) * D + (long)h * HS;
    float* orow = o + obase + (long)qi * D;
#pragma unroll
    for (int d = 0; d < 64; d += 4) {
        float4 v4;
        v4.x = acc[d + 0] * invl; v4.y = acc[d + 1] * invl;
        v4.z = acc[d + 2] * invl; v4.w = acc[d + 3] * invl;
        *(float4*)&orow[d] = v4;
    }
}

// ---------------- Launch ----------------
extern "C" void kernel_launch(void* const* d_in, const int* in_sizes, int n_in,
                              void* d_out, int out_size)
{
    const float* embds = (const float*)d_in[0];
    const float* Wq    = (const float*)d_in[1];
    const float* Wk    = (const float*)d_in[2];
    const float* Wv    = (const float*)d_in[3];
    const float* ln1_g = (const float*)d_in[4];
    const float* ln1_b = (const float*)d_in[5];
    const float* ln2_g = (const float*)d_in[6];
    const float* ln2_b = (const float*)d_in[7];
    const float* W1    = (const float*)d_in[8];
    const float* b1    = (const float*)d_in[9];
    const float* W2    = (const float*)d_in[10];
    const float* b2    = (const float*)d_in[11];
    float* out = (float*)d_out;

    float *px, *pwqkv, *pqkv, *pattn, *px2, *py, *ph;
    cudaGetSymbolAddress((void**)&px,    g_x);
    cudaGetSymbolAddress((void**)&pwqkv, g_wqkv);
    cudaGetSymbolAddress((void**)&pqkv,  g_qkv);
    cudaGetSymbolAddress((void**)&pattn, g_attn);
    cudaGetSymbolAddress((void**)&px2,   g_x2);
    cudaGetSymbolAddress((void**)&py,    g_y);
    cudaGetSymbolAddress((void**)&ph,    g_h);

    // 0) Pack QKV weights: [H,D,HS]x3 -> [D, 3072]
    pack_qkv<<<(D * H * HS) / 256, 256>>>(Wq, Wk, Wv, pwqkv);

    // 1) LN1: x = LN(embds)
    ln_kernel<<<NT, 256>>>(embds, nullptr, ln1_g, ln1_b, px, nullptr);

    // 2) Fused QKV projection: [4096,1024] @ [1024,3072]
    sgemm128<false, false, false><<<dim3(NT / 128, QKVW / 128), 256>>>(
        px, pwqkv, nullptr, nullptr, pqkv, NT, QKVW, D, D, QKVW, QKVW);

    // 3) Causal attention
    attn_kernel<<<dim3(T / 128, Bb * H), 128>>>(pqkv, pattn);

    // 4) Residual + LN2: x2 = embds + attn; y = LN(x2)
    ln_kernel<<<NT, 256>>>(embds, pattn, ln2_g, ln2_b, py, px2);

    // 5) FFN up: h = relu(y @ W1 + b1)
    sgemm128<true, true, false><<<dim3(NT / 128, DFF / 128), 256>>>(
        py, W1, b1, nullptr, ph, NT, DFF, D, D, DFF, DFF);

    // 6) FFN down + residual: out = x2 + h @ W2 + b2
    sgemm128<false, true, true><<<dim3(NT / 128, D / 128), 256>>>(
        ph, W2, b2, px2, out, NT, D, DFF, DFF, D, D);
}

// round 6
// speedup vs baseline: 1.5139x; 1.5139x over previous
#include <cuda_runtime.h>
#include <cuda_bf16.h>
#include <math.h>
#include <stdint.h>

// Problem constants
#define Bb   2
#define T    2048
#define D    1024
#define H    16
#define HS   64
#define NT   (Bb * T)      // 4096 tokens
#define DFF  (4 * D)       // 4096
#define QKVW (3 * D)       // 3072 fused QKV width
#define LNEPS 1e-5f

__device__ __forceinline__ uint32_t smem_to_u32(const void* p) {
    uint32_t a;
    asm("{ .reg .u64 t; cvta.to.shared.u64 t, %1; cvt.u32.u64 %0, t; }" : "=r"(a) : "l"(p));
    return a;
}
__device__ __forceinline__ void cp16(uint32_t dst, const void* src) {
    asm volatile("cp.async.cg.shared.global [%0], [%1], 16;" :: "r"(dst), "l"(src));
}
#define CP_COMMIT() asm volatile("cp.async.commit_group;" ::: "memory")
#define CP_WAIT1()  asm volatile("cp.async.wait_group 1;" ::: "memory")
#define CP_WAIT0()  asm volatile("cp.async.wait_group 0;" ::: "memory")

#define LDM_X4(r0, r1, r2, r3, addr) \
    asm volatile("ldmatrix.sync.aligned.m8n8.x4.shared.b16 {%0,%1,%2,%3}, [%4];" \
        : "=r"(r0), "=r"(r1), "=r"(r2), "=r"(r3) : "r"(addr))

#define MMA16816(c, a, b) \
    asm volatile("mma.sync.aligned.m16n8k16.row.col.f32.bf16.bf16.f32 " \
        "{%0,%1,%2,%3}, {%4,%5,%6,%7}, {%8,%9}, {%0,%1,%2,%3};" \
        : "+f"((c)[0]), "+f"((c)[1]), "+f"((c)[2]), "+f"((c)[3]) \
        : "r"((a)[0]), "r"((a)[1]), "r"((a)[2]), "r"((a)[3]), "r"((b)[0]), "r"((b)[1]))

// ================= Scratch (static device globals) =================
__device__ float g_qkv [(long)NT * QKVW];   // fused QKV fp32
__device__ float g_attn[(long)NT * D];      // attention output
__device__ float g_x2  [(long)NT * D];      // embds + attn
__device__ __nv_bfloat16 g_xh [(long)NT * D],   g_xl [(long)NT * D];    // LN1 out hi/lo
__device__ __nv_bfloat16 g_yh [(long)NT * D],   g_yl [(long)NT * D];    // LN2 out hi/lo
__device__ __nv_bfloat16 g_bqh[(long)QKVW * D], g_bql[(long)QKVW * D];  // QKV W [3072][1024]
__device__ __nv_bfloat16 g_w1h[(long)DFF * D],  g_w1l[(long)DFF * D];   // W1^T [4096][1024]
__device__ __nv_bfloat16 g_w2h[(long)D * DFF],  g_w2l[(long)D * DFF];   // W2^T [1024][4096]
__device__ __nv_bfloat16 g_hh [(long)NT * DFF], g_hl [(long)NT * DFF];  // FFN hidden hi/lo

// ================= Weight prep =================
__global__ __launch_bounds__(256)
void pack_qkv_hl(const float* __restrict__ Wq, const float* __restrict__ Wk,
                 const float* __restrict__ Wv,
                 __nv_bfloat16* __restrict__ bh, __nv_bfloat16* __restrict__ bl)
{
    long idx = (long)blockIdx.x * 256 + threadIdx.x;   // over 3072*1024
    int k = (int)(idx & 1023);
    int n = (int)(idx >> 10);                           // 0..3071
    const float* W = (n < D) ? Wq : (n < 2 * D ? Wk : Wv);
    int nn = n & 1023;
    int h = nn >> 6, e = nn & 63;
    float v = W[(long)h * D * HS + (long)k * HS + e];
    __nv_bfloat16 hi = __float2bfloat16(v);
    bh[idx] = hi;
    bl[idx] = __float2bfloat16(v - __bfloat162float(hi));
}

// Transpose fp32 [RK][RN] -> bf16 hi/lo [RN][RK]
__global__ __launch_bounds__(256)
void transpose_hl(const float* __restrict__ src,
                  __nv_bfloat16* __restrict__ dhi, __nv_bfloat16* __restrict__ dlo,
                  int RK, int RN)
{
    __shared__ float t[32][33];
    int n0 = blockIdx.x * 32, k0 = blockIdx.y * 32;
    int tx = threadIdx.x & 31, ty = threadIdx.x >> 5;   // 32x8
#pragma unroll
    for (int i = 0; i < 4; i++)
        t[ty + i * 8][tx] = src[(long)(k0 + ty + i * 8) * RN + n0 + tx];
    __syncthreads();
#pragma unroll
    for (int i = 0; i < 4; i++) {
        int n = n0 + ty + i * 8, k = k0 + tx;
        float v = t[tx][ty + i * 8];
        __nv_bfloat16 h = __float2bfloat16(v);
        dhi[(long)n * RK + k] = h;
        dlo[(long)n * RK + k] = __float2bfloat16(v - __bfloat162float(h));
    }
}

// ================= LayerNorm -> bf16 hi/lo (optional residual + fp32 copy) ===
__global__ __launch_bounds__(256)
void ln_kernel(const float* __restrict__ x, const float* __restrict__ res,
               const float* __restrict__ gw, const float* __restrict__ bw,
               __nv_bfloat16* __restrict__ yhi, __nv_bfloat16* __restrict__ ylo,
               float* __restrict__ xout)
{
    int row = blockIdx.x;
    int tid = threadIdx.x;
    const float* xr = x + (long)row * D;

    float v[4];
#pragma unroll
    for (int i = 0; i < 4; i++) v[i] = xr[tid + i * 256];
    if (res) {
        const float* rr = res + (long)row * D;
#pragma unroll
        for (int i = 0; i < 4; i++) v[i] += rr[tid + i * 256];
    }
    if (xout) {
        float* xo = xout + (long)row * D;
#pragma unroll
        for (int i = 0; i < 4; i++) xo[tid + i * 256] = v[i];
    }

    __shared__ float red[256];
    float s = (v[0] + v[1]) + (v[2] + v[3]);
    red[tid] = s;
    __syncthreads();
#pragma unroll
    for (int off = 128; off > 0; off >>= 1) {
        if (tid < off) red[tid] += red[tid + off];
        __syncthreads();
    }
    float mean = red[0] * (1.0f / D);
    __syncthreads();
    float sq = 0.f;
#pragma unroll
    for (int i = 0; i < 4; i++) { float dv = v[i] - mean; sq = fmaf(dv, dv, sq); }
    red[tid] = sq;
    __syncthreads();
#pragma unroll
    for (int off = 128; off > 0; off >>= 1) {
        if (tid < off) red[tid] += red[tid + off];
        __syncthreads();
    }
    float var = red[0] * (1.0f / D);
    float inv = rsqrtf(var + LNEPS);

#pragma unroll
    for (int i = 0; i < 4; i++) {
        int c = tid + i * 256;
        float o = (v[i] - mean) * inv * gw[c] + bw[c];
        __nv_bfloat16 h = __float2bfloat16(o);
        yhi[(long)row * D + c] = h;
        ylo[(long)row * D + c] = __float2bfloat16(o - __bfloat162float(h));
    }
}

// ================= Split-bf16 HMMA GEMM (mma.sync, portable target) ========
// C[m][n] = sum_k A[m][k]*B[n][k]  via  Ahi*Bhi + Ahi*Blo + Alo*Bhi
// CTA tile 128x128, BK=32 bf16, 8 warps (2x4), warp tile 64x32, m16n8k16.
// cp.async double-buffered SMEM, 80B row stride (conflict-free ldmatrix).
#define RSB   80                 // smem row stride bytes
#define ABUF  (128 * RSB)        // 10240 bytes per buffer

template<bool RELU, bool HAS_BIAS, bool HAS_RES, bool OUT_BF16>
__global__ __launch_bounds__(256)
void gemm_mma(const __nv_bfloat16* __restrict__ Ahi, const __nv_bfloat16* __restrict__ Alo,
              const __nv_bfloat16* __restrict__ Bhi, const __nv_bfloat16* __restrict__ Blo,
              const float* __restrict__ bias, const float* __restrict__ Res,
              float* __restrict__ C, __nv_bfloat16* __restrict__ Chi, __nv_bfloat16* __restrict__ Clo,
              int K, int lda, int ldb, int ldc)
{
    __shared__ __align__(16) char smA[2 * ABUF];
    __shared__ __align__(16) char smB[2 * ABUF];

    const int tid  = threadIdx.x;
    const int lane = tid & 31, wid = tid >> 5;
    const int wm = wid >> 2, wn = wid & 3;            // warp grid 2x4
    const int row0 = blockIdx.x * 128, col0 = blockIdx.y * 128;

    const uint32_t sA = smem_to_u32(smA);
    const uint32_t sB = smem_to_u32(smB);

    // cp.async mapping: each thread loads rows lr and lr+64, 16B quad lq.
    const int lr = tid >> 2;
    const int lq = tid & 3;
    const uint32_t stA0 = sA + lr * RSB + lq * 16;
    const uint32_t stB0 = sB + lr * RSB + lq * 16;

    // ldmatrix offsets (relative, add buffer base + ks*32)
    const uint32_t aoff = (uint32_t)((wm * 64 + (lane & 15)) * RSB + (lane >> 4) * 16);
    uint32_t boff[2];
#pragma unroll
    for (int jp = 0; jp < 2; jp++) {
        int grp = lane >> 3;
        int rowB = wn * 32 + jp * 16 + ((grp >> 1) << 3) + (lane & 7);
        boff[jp] = (uint32_t)(rowB * RSB + (grp & 1) * 16);
    }

    const int nkc = K >> 5;         // chunks per segment (BK=32)
    const int NCH = 3 * nkc;

    float acc[4][4][4];
#pragma unroll
    for (int i = 0; i < 4; i++)
#pragma unroll
        for (int j = 0; j < 4; j++)
#pragma unroll
            for (int q = 0; q < 4; q++) acc[i][j][q] = 0.f;

#define ISSUE(c)                                                                   \
    {                                                                              \
        int seg_ = (c) / nkc;                                                      \
        long ka_ = (long)((c) - seg_ * nkc) << 5;                                  \
        const __nv_bfloat16* Ap_ = (seg_ < 2) ? Ahi : Alo;                         \
        const __nv_bfloat16* Bp_ = (seg_ == 1) ? Blo : Bhi;                        \
        const char* ga_ = (const char*)(Ap_ + (long)(row0 + lr) * lda + ka_) + lq * 16; \
        const char* gb_ = (const char*)(Bp_ + (long)(col0 + lr) * ldb + ka_) + lq * 16; \
        uint32_t o_ = ((c) & 1) ? ABUF : 0;                                        \
        cp16(stA0 + o_, ga_);                                                      \
        cp16(stA0 + o_ + 64 * RSB, ga_ + (long)64 * lda * 2);                      \
        cp16(stB0 + o_, gb_);                                                      \
        cp16(stB0 + o_ + 64 * RSB, gb_ + (long)64 * ldb * 2);                      \
        CP_COMMIT();                                                               \
    }

    ISSUE(0);
    for (int c = 0; c < NCH; c++) {
        if (c + 1 < NCH) { ISSUE(c + 1); CP_WAIT1(); }
        else             { CP_WAIT0(); }
        __syncthreads();

        const uint32_t off = ((c & 1) ? ABUF : 0);
#pragma unroll
        for (int ks = 0; ks < 2; ks++) {
            uint32_t a[4][4], b[4][2];
#pragma unroll
            for (int i = 0; i < 4; i++) {
                uint32_t ad = sA + off + aoff + i * (16 * RSB) + ks * 32;
                LDM_X4(a[i][0], a[i][1], a[i][2], a[i][3], ad);
            }
#pragma unroll
            for (int jp = 0; jp < 2; jp++) {
                uint32_t bd = sB + off + boff[jp] + ks * 32;
                LDM_X4(b[2 * jp][0], b[2 * jp][1], b[2 * jp + 1][0], b[2 * jp + 1][1], bd);
            }
#pragma unroll
            for (int i = 0; i < 4; i++)
#pragma unroll
                for (int j = 0; j < 4; j++)
                    MMA16816(acc[i][j], a[i], b[j]);
        }
        __syncthreads();
    }
#undef ISSUE

    // Epilogue: thread holds (m = base + i*16 + lane/4 (+8), n = base + j*8 + 2*(lane%4))
    const int mb = row0 + wm * 64 + (lane >> 2);
    const int nb = col0 + wn * 32 + (lane & 3) * 2;

#pragma unroll
    for (int i = 0; i < 4; i++) {
#pragma unroll
        for (int half = 0; half < 2; half++) {
            const int m = mb + i * 16 + half * 8;
#pragma unroll
            for (int j = 0; j < 4; j++) {
                const int n = nb + j * 8;
                float v0 = acc[i][j][half * 2 + 0];
                float v1 = acc[i][j][half * 2 + 1];
                if (HAS_BIAS) { v0 += __ldg(&bias[n]); v1 += __ldg(&bias[n + 1]); }
                if (RELU)     { v0 = fmaxf(v0, 0.f); v1 = fmaxf(v1, 0.f); }
                if (HAS_RES) {
                    const float2 r2 = *(const float2*)&Res[(long)m * ldc + n];
                    v0 += r2.x; v1 += r2.y;
                }
                if (OUT_BF16) {
                    __nv_bfloat16 h0 = __float2bfloat16(v0);
                    __nv_bfloat16 h1 = __float2bfloat16(v1);
                    __nv_bfloat16 l0 = __float2bfloat16(v0 - __bfloat162float(h0));
                    __nv_bfloat16 l1 = __float2bfloat16(v1 - __bfloat162float(h1));
                    uint32_t ph = ((uint32_t)__bfloat16_as_ushort(h1) << 16) | __bfloat16_as_ushort(h0);
                    uint32_t pl = ((uint32_t)__bfloat16_as_ushort(l1) << 16) | __bfloat16_as_ushort(l0);
                    *(uint32_t*)(Chi + (long)m * ldc + n) = ph;
                    *(uint32_t*)(Clo + (long)m * ldc + n) = pl;
                } else {
                    float2 o; o.x = v0; o.y = v1;
                    *(float2*)&C[(long)m * ldc + n] = o;
                }
            }
        }
    }
}

// ================= Causal flash attention (fp32) =================
__global__ __launch_bounds__(128)
void attn_kernel(const float* __restrict__ qkv, float* __restrict__ o)
{
    __shared__ float ksh[64][64];
    __shared__ float vsh[64][64];

    int b  = blockIdx.y / H;
    int h  = blockIdx.y % H;
    int q0 = blockIdx.x * 128;
    int tid = threadIdx.x;
    int qi = q0 + tid;

    long qbase = ((long)b * T) * QKVW + (long)h * HS;
    long kbase = qbase + D;
    long vbase = qbase + 2 * D;

    float qr[64];
    const float* qrow = qkv + qbase + (long)qi * QKVW;
#pragma unroll
    for (int d = 0; d < 64; d += 4) {
        float4 v4 = *(const float4*)&qrow[d];
        qr[d] = v4.x; qr[d + 1] = v4.y; qr[d + 2] = v4.z; qr[d + 3] = v4.w;
    }

    float acc[64];
#pragma unroll
    for (int d = 0; d < 64; d++) acc[d] = 0.f;
    float m = -INFINITY, l = 0.f;
    const float scale = 0.03125f;            // D^-0.5

    int ntiles = (q0 + 128) / 64;
    for (int t0 = 0; t0 < ntiles; t0++) {
        int k0 = t0 * 64;
        __syncthreads();
        for (int idx = tid; idx < 64 * 16; idx += 128) {
            int r = idx >> 4, c4 = (idx & 15) * 4;
            *(float4*)&ksh[r][c4] = *(const float4*)&qkv[kbase + (long)(k0 + r) * QKVW + c4];
            *(float4*)&vsh[r][c4] = *(const float4*)&qkv[vbase + (long)(k0 + r) * QKVW + c4];
        }
        __syncthreads();

        int jend = qi - k0 + 1;
        if (jend > 64) jend = 64;
        for (int j = 0; j < jend; j++) {
            float s0 = 0.f, s1 = 0.f, s2 = 0.f, s3 = 0.f;
#pragma unroll
            for (int d = 0; d < 64; d += 4) {
                s0 = fmaf(qr[d], ksh[j][d], s0);
                s1 = fmaf(qr[d + 1], ksh[j][d + 1], s1);
                s2 = fmaf(qr[d + 2], ksh[j][d + 2], s2);
                s3 = fmaf(qr[d + 3], ksh[j][d + 3], s3);
            }
            float s = ((s0 + s1) + (s2 + s3)) * scale;
            if (s > m) {
                float corr = __expf(m - s);
                l *= corr;
#pragma unroll
                for (int d = 0; d < 64; d++) acc[d] *= corr;
                m = s;
            }
            float p = __expf(s - m);
            l += p;
#pragma unroll
            for (int d = 0; d < 64; d++)
                acc[d] = fmaf(p, vsh[j][d], acc[d]);
        }
    }

    float invl = 1.f / l;
    long obase = ((long)b * T) * D + (long)h * HS;
    float* orow = o + obase + (long)qi * D;
#pragma unroll
    for (int d = 0; d < 64; d += 4) {
        float4 v4;
        v4.x = acc[d] * invl; v4.y = acc[d + 1] * invl;
        v4.z = acc[d + 2] * invl; v4.w = acc[d + 3] * invl;
        *(float4*)&orow[d] = v4;
    }
}

// ================= Launch =================
extern "C" void kernel_launch(void* const* d_in, const int* in_sizes, int n_in,
                              void* d_out, int out_size)
{
    const float* embds = (const float*)d_in[0];
    const float* Wq    = (const float*)d_in[1];
    const float* Wk    = (const float*)d_in[2];
    const float* Wv    = (const float*)d_in[3];
    const float* ln1_g = (const float*)d_in[4];
    const float* ln1_b = (const float*)d_in[5];
    const float* ln2_g = (const float*)d_in[6];
    const float* ln2_b = (const float*)d_in[7];
    const float* W1    = (const float*)d_in[8];
    const float* b1    = (const float*)d_in[9];
    const float* W2    = (const float*)d_in[10];
    const float* b2    = (const float*)d_in[11];
    float* out = (float*)d_out;

    float *pqkv, *pattn, *px2;
    __nv_bfloat16 *pxh, *pxl, *pyh, *pyl, *pbqh, *pbql, *pw1h, *pw1l, *pw2h, *pw2l, *phh, *phl;
    cudaGetSymbolAddress((void**)&pqkv,  g_qkv);
    cudaGetSymbolAddress((void**)&pattn, g_attn);
    cudaGetSymbolAddress((void**)&px2,   g_x2);
    cudaGetSymbolAddress((void**)&pxh,   g_xh);
    cudaGetSymbolAddress((void**)&pxl,   g_xl);
    cudaGetSymbolAddress((void**)&pyh,   g_yh);
    cudaGetSymbolAddress((void**)&pyl,   g_yl);
    cudaGetSymbolAddress((void**)&pbqh,  g_bqh);
    cudaGetSymbolAddress((void**)&pbql,  g_bql);
    cudaGetSymbolAddress((void**)&pw1h,  g_w1h);
    cudaGetSymbolAddress((void**)&pw1l,  g_w1l);
    cudaGetSymbolAddress((void**)&pw2h,  g_w2h);
    cudaGetSymbolAddress((void**)&pw2l,  g_w2l);
    cudaGetSymbolAddress((void**)&phh,   g_hh);
    cudaGetSymbolAddress((void**)&phl,   g_hl);

    // 0) Weight prep (hi/lo bf16, [N][K] layout)
    pack_qkv_hl<<<(QKVW * D) / 256, 256>>>(Wq, Wk, Wv, pbqh, pbql);
    transpose_hl<<<dim3(DFF / 32, D / 32), 256>>>(W1, pw1h, pw1l, D, DFF);
    transpose_hl<<<dim3(D / 32, DFF / 32), 256>>>(W2, pw2h, pw2l, DFF, D);

    // 1) LN1 -> x hi/lo
    ln_kernel<<<NT, 256>>>(embds, nullptr, ln1_g, ln1_b, pxh, pxl, nullptr);

    // 2) QKV: [4096,1024] x [3072,1024]^T -> qkv fp32
    gemm_mma<false, false, false, false><<<dim3(NT / 128, QKVW / 128), 256>>>(
        pxh, pxl, pbqh, pbql, nullptr, nullptr, pqkv, nullptr, nullptr, D, D, D, QKVW);

    // 3) Causal attention
    attn_kernel<<<dim3(T / 128, Bb * H), 128>>>(pqkv, pattn);

    // 4) Residual + LN2 -> y hi/lo, x2 fp32
    ln_kernel<<<NT, 256>>>(embds, pattn, ln2_g, ln2_b, pyh, pyl, px2);

    // 5) FFN up: relu(y @ W1 + b1) -> h hi/lo bf16
    gemm_mma<true, true, false, true><<<dim3(NT / 128, DFF / 128), 256>>>(
        pyh, pyl, pw1h, pw1l, b1, nullptr, nullptr, phh, phl, D, D, D, DFF);

    // 6) FFN down + bias + residual -> out fp32
    gemm_mma<false, true, true, false><<<dim3(NT / 128, D / 128), 256>>>(
        phh, phl, pw2h, pw2l, b2, px2, out, nullptr, nullptr, DFF, DFF, DFF, D);
}

// round 13
// speedup vs baseline: 2.1569x; 1.4247x over previous
#include <cuda_runtime.h>
#include <cuda_bf16.h>
#include <math.h>
#include <stdint.h>

// Problem constants
#define Bb   2
#define T    2048
#define D    1024
#define H    16
#define HS   64
#define NT   (Bb * T)      // 4096 tokens
#define DFF  (4 * D)       // 4096
#define QKVW (3 * D)       // 3072 fused QKV width
#define LNEPS 1e-5f
#define ASCALE 0.03125f    // D^-0.5

__device__ __forceinline__ uint32_t smem_to_u32(const void* p) {
    uint32_t a;
    asm("{ .reg .u64 t; cvta.to.shared.u64 t, %1; cvt.u32.u64 %0, t; }" : "=r"(a) : "l"(p));
    return a;
}
__device__ __forceinline__ void cp16(uint32_t dst, const void* src) {
    asm volatile("cp.async.cg.shared.global [%0], [%1], 16;" :: "r"(dst), "l"(src));
}
#define CP_COMMIT() asm volatile("cp.async.commit_group;" ::: "memory")
#define CP_WAIT1()  asm volatile("cp.async.wait_group 1;" ::: "memory")
#define CP_WAIT0()  asm volatile("cp.async.wait_group 0;" ::: "memory")

#define LDM_X4(r0, r1, r2, r3, addr) \
    asm volatile("ldmatrix.sync.aligned.m8n8.x4.shared.b16 {%0,%1,%2,%3}, [%4];" \
        : "=r"(r0), "=r"(r1), "=r"(r2), "=r"(r3) : "r"(addr))
#define LDM_X2(r0, r1, addr) \
    asm volatile("ldmatrix.sync.aligned.m8n8.x2.shared.b16 {%0,%1}, [%2];" \
        : "=r"(r0), "=r"(r1) : "r"(addr))
#define LDM_X2T(r0, r1, addr) \
    asm volatile("ldmatrix.sync.aligned.m8n8.x2.trans.shared.b16 {%0,%1}, [%2];" \
        : "=r"(r0), "=r"(r1) : "r"(addr))

#define MMA16816(c, a, b) \
    asm volatile("mma.sync.aligned.m16n8k16.row.col.f32.bf16.bf16.f32 " \
        "{%0,%1,%2,%3}, {%4,%5,%6,%7}, {%8,%9}, {%0,%1,%2,%3};" \
        : "+f"((c)[0]), "+f"((c)[1]), "+f"((c)[2]), "+f"((c)[3]) \
        : "r"((a)[0]), "r"((a)[1]), "r"((a)[2]), "r"((a)[3]), "r"((b)[0]), "r"((b)[1]))

__device__ __forceinline__ uint32_t packbf(float lo, float hi) {
    __nv_bfloat162 t = __floats2bfloat162_rn(lo, hi);
    return *(uint32_t*)&t;
}

// ================= Scratch (static device globals) =================
__device__ float g_attn[(long)NT * D];      // attention output
__device__ float g_x2  [(long)NT * D];      // embds + attn
__device__ __nv_bfloat16 g_xh [(long)NT * D],    g_xl [(long)NT * D];     // LN1 out hi/lo
__device__ __nv_bfloat16 g_yh [(long)NT * D],    g_yl [(long)NT * D];     // LN2 out hi/lo
__device__ __nv_bfloat16 g_qvh[(long)NT * QKVW], g_qvl[(long)NT * QKVW];  // QKV hi/lo
__device__ __nv_bfloat16 g_bqh[(long)QKVW * D],  g_bql[(long)QKVW * D];   // QKV W [3072][1024]
__device__ __nv_bfloat16 g_w1h[(long)DFF * D],   g_w1l[(long)DFF * D];    // W1^T [4096][1024]
__device__ __nv_bfloat16 g_w2h[(long)D * DFF],   g_w2l[(long)D * DFF];    // W2^T [1024][4096]
__device__ __nv_bfloat16 g_hh [(long)NT * DFF],  g_hl [(long)NT * DFF];   // FFN hidden hi/lo

// ================= Weight prep =================
__global__ __launch_bounds__(256)
void pack_qkv_hl(const float* __restrict__ Wq, const float* __restrict__ Wk,
                 const float* __restrict__ Wv,
                 __nv_bfloat16* __restrict__ bh, __nv_bfloat16* __restrict__ bl)
{
    long idx = (long)blockIdx.x * 256 + threadIdx.x;   // over 3072*1024
    int k = (int)(idx & 1023);
    int n = (int)(idx >> 10);                           // 0..3071
    const float* W = (n < D) ? Wq : (n < 2 * D ? Wk : Wv);
    int nn = n & 1023;
    int h = nn >> 6, e = nn & 63;
    float v = W[(long)h * D * HS + (long)k * HS + e];
    __nv_bfloat16 hi = __float2bfloat16(v);
    bh[idx] = hi;
    bl[idx] = __float2bfloat16(v - __bfloat162float(hi));
}

__global__ __launch_bounds__(256)
void transpose_hl(const float* __restrict__ src,
                  __nv_bfloat16* __restrict__ dhi, __nv_bfloat16* __restrict__ dlo,
                  int RK, int RN)
{
    __shared__ float t[32][33];
    int n0 = blockIdx.x * 32, k0 = blockIdx.y * 32;
    int tx = threadIdx.x & 31, ty = threadIdx.x >> 5;
#pragma unroll
    for (int i = 0; i < 4; i++)
        t[ty + i * 8][tx] = src[(long)(k0 + ty + i * 8) * RN + n0 + tx];
    __syncthreads();
#pragma unroll
    for (int i = 0; i < 4; i++) {
        int n = n0 + ty + i * 8, k = k0 + tx;
        float v = t[tx][ty + i * 8];
        __nv_bfloat16 h = __float2bfloat16(v);
        dhi[(long)n * RK + k] = h;
        dlo[(long)n * RK + k] = __float2bfloat16(v - __bfloat162float(h));
    }
}

// ================= LayerNorm -> bf16 hi/lo =================
__global__ __launch_bounds__(256)
void ln_kernel(const float* __restrict__ x, const float* __restrict__ res,
               const float* __restrict__ gw, const float* __restrict__ bw,
               __nv_bfloat16* __restrict__ yhi, __nv_bfloat16* __restrict__ ylo,
               float* __restrict__ xout)
{
    int row = blockIdx.x;
    int tid = threadIdx.x;
    const float* xr = x + (long)row * D;

    float v[4];
#pragma unroll
    for (int i = 0; i < 4; i++) v[i] = xr[tid + i * 256];
    if (res) {
        const float* rr = res + (long)row * D;
#pragma unroll
        for (int i = 0; i < 4; i++) v[i] += rr[tid + i * 256];
    }
    if (xout) {
        float* xo = xout + (long)row * D;
#pragma unroll
        for (int i = 0; i < 4; i++) xo[tid + i * 256] = v[i];
    }

    __shared__ float red[256];
    float s = (v[0] + v[1]) + (v[2] + v[3]);
    red[tid] = s;
    __syncthreads();
#pragma unroll
    for (int off = 128; off > 0; off >>= 1) {
        if (tid < off) red[tid] += red[tid + off];
        __syncthreads();
    }
    float mean = red[0] * (1.0f / D);
    __syncthreads();
    float sq = 0.f;
#pragma unroll
    for (int i = 0; i < 4; i++) { float dv = v[i] - mean; sq = fmaf(dv, dv, sq); }
    red[tid] = sq;
    __syncthreads();
#pragma unroll
    for (int off = 128; off > 0; off >>= 1) {
        if (tid < off) red[tid] += red[tid + off];
        __syncthreads();
    }
    float var = red[0] * (1.0f / D);
    float inv = rsqrtf(var + LNEPS);

#pragma unroll
    for (int i = 0; i < 4; i++) {
        int c = tid + i * 256;
        float o = (v[i] - mean) * inv * gw[c] + bw[c];
        __nv_bfloat16 h = __float2bfloat16(o);
        yhi[(long)row * D + c] = h;
        ylo[(long)row * D + c] = __float2bfloat16(o - __bfloat162float(h));
    }
}

// ================= Split-bf16 HMMA GEMM =================
#define RSB   80
#define ABUF  (128 * RSB)

template<bool RELU, bool HAS_BIAS, bool HAS_RES, bool OUT_BF16>
__global__ __launch_bounds__(256)
void gemm_mma(const __nv_bfloat16* __restrict__ Ahi, const __nv_bfloat16* __restrict__ Alo,
              const __nv_bfloat16* __restrict__ Bhi, const __nv_bfloat16* __restrict__ Blo,
              const float* __restrict__ bias, const float* __restrict__ Res,
              float* __restrict__ C, __nv_bfloat16* __restrict__ Chi, __nv_bfloat16* __restrict__ Clo,
              int K, int lda, int ldb, int ldc)
{
    __shared__ __align__(16) char smA[2 * ABUF];
    __shared__ __align__(16) char smB[2 * ABUF];

    const int tid  = threadIdx.x;
    const int lane = tid & 31, wid = tid >> 5;
    const int wm = wid >> 2, wn = wid & 3;
    const int row0 = blockIdx.x * 128, col0 = blockIdx.y * 128;

    const uint32_t sA = smem_to_u32(smA);
    const uint32_t sB = smem_to_u32(smB);

    const int lr = tid >> 2;
    const int lq = tid & 3;
    const uint32_t stA0 = sA + lr * RSB + lq * 16;
    const uint32_t stB0 = sB + lr * RSB + lq * 16;

    const uint32_t aoff = (uint32_t)((wm * 64 + (lane & 15)) * RSB + (lane >> 4) * 16);
    uint32_t boff[2];
#pragma unroll
    for (int jp = 0; jp < 2; jp++) {
        int grp = lane >> 3;
        int rowB = wn * 32 + jp * 16 + ((grp >> 1) << 3) + (lane & 7);
        boff[jp] = (uint32_t)(rowB * RSB + (grp & 1) * 16);
    }

    const int nkc = K >> 5;
    const int NCH = 3 * nkc;

    float acc[4][4][4];
#pragma unroll
    for (int i = 0; i < 4; i++)
#pragma unroll
        for (int j = 0; j < 4; j++)
#pragma unroll
            for (int q = 0; q < 4; q++) acc[i][j][q] = 0.f;

#define ISSUE(c)                                                                   \
    {                                                                              \
        int seg_ = (c) / nkc;                                                      \
        long ka_ = (long)((c) - seg_ * nkc) << 5;                                  \
        const __nv_bfloat16* Ap_ = (seg_ < 2) ? Ahi : Alo;                         \
        const __nv_bfloat16* Bp_ = (seg_ == 1) ? Blo : Bhi;                        \
        const char* ga_ = (const char*)(Ap_ + (long)(row0 + lr) * lda + ka_) + lq * 16; \
        const char* gb_ = (const char*)(Bp_ + (long)(col0 + lr) * ldb + ka_) + lq * 16; \
        uint32_t o_ = ((c) & 1) ? ABUF : 0;                                        \
        cp16(stA0 + o_, ga_);                                                      \
        cp16(stA0 + o_ + 64 * RSB, ga_ + (long)64 * lda * 2);                      \
        cp16(stB0 + o_, gb_);                                                      \
        cp16(stB0 + o_ + 64 * RSB, gb_ + (long)64 * ldb * 2);                      \
        CP_COMMIT();                                                               \
    }

    ISSUE(0);
    for (int c = 0; c < NCH; c++) {
        if (c + 1 < NCH) { ISSUE(c + 1); CP_WAIT1(); }
        else             { CP_WAIT0(); }
        __syncthreads();

        const uint32_t off = ((c & 1) ? ABUF : 0);
#pragma unroll
        for (int ks = 0; ks < 2; ks++) {
            uint32_t a[4][4], b[4][2];
#pragma unroll
            for (int i = 0; i < 4; i++) {
                uint32_t ad = sA + off + aoff + i * (16 * RSB) + ks * 32;
                LDM_X4(a[i][0], a[i][1], a[i][2], a[i][3], ad);
            }
#pragma unroll
            for (int jp = 0; jp < 2; jp++) {
                uint32_t bd = sB + off + boff[jp] + ks * 32;
                LDM_X4(b[2 * jp][0], b[2 * jp][1], b[2 * jp + 1][0], b[2 * jp + 1][1], bd);
            }
#pragma unroll
            for (int i = 0; i < 4; i++)
#pragma unroll
                for (int j = 0; j < 4; j++)
                    MMA16816(acc[i][j], a[i], b[j]);
        }
        __syncthreads();
    }
#undef ISSUE

    const int mb = row0 + wm * 64 + (lane >> 2);
    const int nb = col0 + wn * 32 + (lane & 3) * 2;

#pragma unroll
    for (int i = 0; i < 4; i++) {
#pragma unroll
        for (int half = 0; half < 2; half++) {
            const int m = mb + i * 16 + half * 8;
#pragma unroll
            for (int j = 0; j < 4; j++) {
                const int n = nb + j * 8;
                float v0 = acc[i][j][half * 2 + 0];
                float v1 = acc[i][j][half * 2 + 1];
                if (HAS_BIAS) { v0 += __ldg(&bias[n]); v1 += __ldg(&bias[n + 1]); }
                if (RELU)     { v0 = fmaxf(v0, 0.f); v1 = fmaxf(v1, 0.f); }
                if (HAS_RES) {
                    const float2 r2 = *(const float2*)&Res[(long)m * ldc + n];
                    v0 += r2.x; v1 += r2.y;
                }
                if (OUT_BF16) {
                    __nv_bfloat16 h0 = __float2bfloat16(v0);
                    __nv_bfloat16 h1 = __float2bfloat16(v1);
                    __nv_bfloat16 l0 = __float2bfloat16(v0 - __bfloat162float(h0));
                    __nv_bfloat16 l1 = __float2bfloat16(v1 - __bfloat162float(h1));
                    uint32_t ph = ((uint32_t)__bfloat16_as_ushort(h1) << 16) | __bfloat16_as_ushort(h0);
                    uint32_t pl = ((uint32_t)__bfloat16_as_ushort(l1) << 16) | __bfloat16_as_ushort(l0);
                    *(uint32_t*)(Chi + (long)m * ldc + n) = ph;
                    *(uint32_t*)(Clo + (long)m * ldc + n) = pl;
                } else {
                    float2 o; o.x = v0; o.y = v1;
                    *(float2*)&C[(long)m * ldc + n] = o;
                }
            }
        }
    }
}

// ================= HMMA flash attention (split-bf16) =================
// CTA: 4 warps x m16 = 64 query rows. K/V 64x64 hi/lo tiles double-buffered.
// smem layout (dynamic): QH 0, QL 9216, buf b at 18432+b*36864: KH+0, KL+9216, VH+18432, VL+27648
#define ATT_RS   144
#define ATT_TILE 9216
#define ATT_SM   92160

__global__ __launch_bounds__(128)
void attn_mma(const __nv_bfloat16* __restrict__ qkvh, const __nv_bfloat16* __restrict__ qkvl,
              float* __restrict__ o)
{
    extern __shared__ char sm[];
    const uint32_t sbase = smem_to_u32(sm);
    const int tid = threadIdx.x, lane = tid & 31, wid = tid >> 5;
    const int b = blockIdx.y / H, h = blockIdx.y % H;
    const int q0 = blockIdx.x * 64;

    const long base_q = ((long)b * T) * QKVW + h * HS;
    const long base_k = base_q + D;
    const long base_v = base_q + 2 * D;

    const int lrow = tid >> 3, lchunk = tid & 7;

    // Prologue: Q tile (hi/lo)
#pragma unroll
    for (int i = 0; i < 4; i++) {
        int r = lrow + i * 16;
        long src = base_q + (long)(q0 + r) * QKVW + lchunk * 8;
        cp16(sbase + r * ATT_RS + lchunk * 16, qkvh + src);
        cp16(sbase + ATT_TILE + r * ATT_RS + lchunk * 16, qkvl + src);
    }
    CP_COMMIT();

#define LOADKV(kt, bb)                                                          \
    {                                                                           \
        _Pragma("unroll")                                                       \
        for (int i = 0; i < 4; i++) {                                           \
            int r = lrow + i * 16;                                              \
            long srk = base_k + (long)((kt) * 64 + r) * QKVW + lchunk * 8;      \
            long srv = base_v + (long)((kt) * 64 + r) * QKVW + lchunk * 8;      \
            uint32_t d_ = (bb) + r * ATT_RS + lchunk * 16;                      \
            cp16(d_, qkvh + srk);                                               \
            cp16(d_ + ATT_TILE, qkvl + srk);                                    \
            cp16(d_ + 2 * ATT_TILE, qkvh + srv);                                \
            cp16(d_ + 3 * ATT_TILE, qkvl + srv);                                \
        }                                                                       \
        CP_COMMIT();                                                            \
    }

    LOADKV(0, sbase + 2 * ATT_TILE);
    CP_WAIT1();           // Q ready
    __syncthreads();

    // Q fragments (A-layout m16k16 per k-chunk)
    uint32_t qh[4][4], ql[4][4];
#pragma unroll
    for (int kc = 0; kc < 4; kc++) {
        uint32_t adr = sbase + (wid * 16 + (lane & 15)) * ATT_RS + (lane >> 4) * 16 + kc * 32;
        LDM_X4(qh[kc][0], qh[kc][1], qh[kc][2], qh[kc][3], adr);
        LDM_X4(ql[kc][0], ql[kc][1], ql[kc][2], ql[kc][3], adr + ATT_TILE);
    }

    float m0 = -1e30f, m1 = -1e30f, l0 = 0.f, l1 = 0.f;
    float oa[8][4];
#pragma unroll
    for (int dn = 0; dn < 8; dn++)
#pragma unroll
        for (int q = 0; q < 4; q++) oa[dn][q] = 0.f;

    const int qi0   = q0 + wid * 16 + (lane >> 2);
    const int qimax = q0 + wid * 16 + 15;
    const int ntiles = blockIdx.x + 1;

    for (int kt = 0; kt < ntiles; kt++) {
        const uint32_t bb = sbase + 2 * ATT_TILE + (uint32_t)(kt & 1) * (4 * ATT_TILE);
        if (kt + 1 < ntiles) {
            LOADKV(kt + 1, sbase + 2 * ATT_TILE + (uint32_t)((kt + 1) & 1) * (4 * ATT_TILE));
            CP_WAIT1();
        } else {
            CP_WAIT0();
        }
        __syncthreads();

        const int k0 = kt * 64;
        if (k0 <= qimax) {
            const bool diag = (k0 + 63 > q0 + wid * 16);
            float p[8][4];

            // ---- scores = Q K^T (3-pass split) ----
#pragma unroll
            for (int j = 0; j < 8; j++) {
                float c[4] = {0.f, 0.f, 0.f, 0.f};
                if (k0 + j * 8 <= qimax) {
#pragma unroll
                    for (int kc = 0; kc < 4; kc++) {
                        uint32_t adr = bb + (j * 8 + (lane & 7)) * ATT_RS
                                     + ((lane >> 3) & 1) * 16 + kc * 32;
                        uint32_t kh0, kh1, kl0, kl1;
                        LDM_X2(kh0, kh1, adr);
                        LDM_X2(kl0, kl1, adr + ATT_TILE);
                        uint32_t bh[2] = {kh0, kh1}, bl[2] = {kl0, kl1};
                        MMA16816(c, qh[kc], bh);
                        MMA16816(c, qh[kc], bl);
                        MMA16816(c, ql[kc], bh);
                    }
                } else {
                    c[0] = c[1] = c[2] = c[3] = -1e30f;
                }
                p[j][0] = c[0]; p[j][1] = c[1]; p[j][2] = c[2]; p[j][3] = c[3];
            }

            // ---- causal mask on diagonal tiles ----
            if (diag) {
#pragma unroll
                for (int j = 0; j < 8; j++) {
                    int cb = k0 + j * 8 + 2 * (lane & 3);
                    if (cb     > qi0)     p[j][0] = -1e30f;
                    if (cb + 1 > qi0)     p[j][1] = -1e30f;
                    if (cb     > qi0 + 8) p[j][2] = -1e30f;
                    if (cb + 1 > qi0 + 8) p[j][3] = -1e30f;
                }
            }

            // ---- online softmax (raw scores; scale folded into exp) ----
            float mx0 = -1e30f, mx1 = -1e30f;
#pragma unroll
            for (int j = 0; j < 8; j++) {
                mx0 = fmaxf(mx0, fmaxf(p[j][0], p[j][1]));
                mx1 = fmaxf(mx1, fmaxf(p[j][2], p[j][3]));
            }
            mx0 = fmaxf(mx0, __shfl_xor_sync(0xFFFFFFFFu, mx0, 1));
            mx0 = fmaxf(mx0, __shfl_xor_sync(0xFFFFFFFFu, mx0, 2));
            mx1 = fmaxf(mx1, __shfl_xor_sync(0xFFFFFFFFu, mx1, 1));
            mx1 = fmaxf(mx1, __shfl_xor_sync(0xFFFFFFFFu, mx1, 2));

            float mn0 = fmaxf(m0, mx0), mn1 = fmaxf(m1, mx1);
            float cr0 = __expf((m0 - mn0) * ASCALE);
            float cr1 = __expf((m1 - mn1) * ASCALE);
            m0 = mn0; m1 = mn1;

            float s0 = 0.f, s1 = 0.f;
#pragma unroll
            for (int j = 0; j < 8; j++) {
                p[j][0] = __expf((p[j][0] - mn0) * ASCALE);
                p[j][1] = __expf((p[j][1] - mn0) * ASCALE);
                p[j][2] = __expf((p[j][2] - mn1) * ASCALE);
                p[j][3] = __expf((p[j][3] - mn1) * ASCALE);
                s0 += p[j][0] + p[j][1];
                s1 += p[j][2] + p[j][3];
            }
            s0 += __shfl_xor_sync(0xFFFFFFFFu, s0, 1);
            s0 += __shfl_xor_sync(0xFFFFFFFFu, s0, 2);
            s1 += __shfl_xor_sync(0xFFFFFFFFu, s1, 1);
            s1 += __shfl_xor_sync(0xFFFFFFFFu, s1, 2);
            l0 = l0 * cr0 + s0;
            l1 = l1 * cr1 + s1;

#pragma unroll
            for (int dn = 0; dn < 8; dn++) {
                oa[dn][0] *= cr0; oa[dn][1] *= cr0;
                oa[dn][2] *= cr1; oa[dn][3] *= cr1;
            }

            // ---- pack P into A-fragments (hi/lo) ----
            uint32_t ph[4][4], pl[4][4];
#pragma unroll
            for (int tk = 0; tk < 4; tk++) {
#pragma unroll
                for (int u = 0; u < 4; u++) {
                    int j = 2 * tk + (u >> 1);
                    float a0 = p[j][(u & 1) * 2], a1 = p[j][(u & 1) * 2 + 1];
                    __nv_bfloat16 h0 = __float2bfloat16(a0);
                    __nv_bfloat16 h1 = __float2bfloat16(a1);
                    ph[tk][u] = ((uint32_t)__bfloat16_as_ushort(h1) << 16) | __bfloat16_as_ushort(h0);
                    pl[tk][u] = packbf(a0 - __bfloat162float(h0), a1 - __bfloat162float(h1));
                }
            }

            // ---- O += P V (3-pass split), V^T fragments via ldmatrix.trans ----
#pragma unroll
            for (int dn = 0; dn < 8; dn++) {
#pragma unroll
                for (int tk = 0; tk < 4; tk++) {
                    if (k0 + tk * 16 <= qimax) {
                        uint32_t adr = bb + 2 * ATT_TILE + (tk * 16 + (lane & 15)) * ATT_RS + dn * 16;
                        uint32_t vh0, vh1, vl0, vl1;
                        LDM_X2T(vh0, vh1, adr);
                        LDM_X2T(vl0, vl1, adr + ATT_TILE);
                        uint32_t bh[2] = {vh0, vh1}, bl[2] = {vl0, vl1};
                        MMA16816(oa[dn], ph[tk], bh);
                        MMA16816(oa[dn], ph[tk], bl);
                        MMA16816(oa[dn], pl[tk], bh);
                    }
                }
            }
        }
        __syncthreads();
    }
#undef LOADKV

    const float il0 = 1.f / l0, il1 = 1.f / l1;
    const long ob = ((long)b * T) * D + h * HS;
#pragma unroll
    for (int dn = 0; dn < 8; dn++) {
        int d = dn * 8 + 2 * (lane & 3);
        float2 v0, v1;
        v0.x = oa[dn][0] * il0; v0.y = oa[dn][1] * il0;
        v1.x = oa[dn][2] * il1; v1.y = oa[dn][3] * il1;
        *(float2*)&o[ob + (long)qi0 * D + d] = v0;
        *(float2*)&o[ob + (long)(qi0 + 8) * D + d] = v1;
    }
}

// ================= Launch =================
extern "C" void kernel_launch(void* const* d_in, const int* in_sizes, int n_in,
                              void* d_out, int out_size)
{
    const float* embds = (const float*)d_in[0];
    const float* Wq    = (const float*)d_in[1];
    const float* Wk    = (const float*)d_in[2];
    const float* Wv    = (const float*)d_in[3];
    const float* ln1_g = (const float*)d_in[4];
    const float* ln1_b = (const float*)d_in[5];
    const float* ln2_g = (const float*)d_in[6];
    const float* ln2_b = (const float*)d_in[7];
    const float* W1    = (const float*)d_in[8];
    const float* b1    = (const float*)d_in[9];
    const float* W2    = (const float*)d_in[10];
    const float* b2    = (const float*)d_in[11];
    float* out = (float*)d_out;

    float *pattn, *px2;
    __nv_bfloat16 *pxh, *pxl, *pyh, *pyl, *pqvh, *pqvl, *pbqh, *pbql, *pw1h, *pw1l, *pw2h, *pw2l, *phh, *phl;
    cudaGetSymbolAddress((void**)&pattn, g_attn);
    cudaGetSymbolAddress((void**)&px2,   g_x2);
    cudaGetSymbolAddress((void**)&pxh,   g_xh);
    cudaGetSymbolAddress((void**)&pxl,   g_xl);
    cudaGetSymbolAddress((void**)&pyh,   g_yh);
    cudaGetSymbolAddress((void**)&pyl,   g_yl);
    cudaGetSymbolAddress((void**)&pqvh,  g_qvh);
    cudaGetSymbolAddress((void**)&pqvl,  g_qvl);
    cudaGetSymbolAddress((void**)&pbqh,  g_bqh);
    cudaGetSymbolAddress((void**)&pbql,  g_bql);
    cudaGetSymbolAddress((void**)&pw1h,  g_w1h);
    cudaGetSymbolAddress((void**)&pw1l,  g_w1l);
    cudaGetSymbolAddress((void**)&pw2h,  g_w2h);
    cudaGetSymbolAddress((void**)&pw2l,  g_w2l);
    cudaGetSymbolAddress((void**)&phh,   g_hh);
    cudaGetSymbolAddress((void**)&phl,   g_hl);

    cudaFuncSetAttribute(attn_mma, cudaFuncAttributeMaxDynamicSharedMemorySize, ATT_SM);

    // 0) Weight prep
    pack_qkv_hl<<<(QKVW * D) / 256, 256>>>(Wq, Wk, Wv, pbqh, pbql);
    transpose_hl<<<dim3(DFF / 32, D / 32), 256>>>(W1, pw1h, pw1l, D, DFF);
    transpose_hl<<<dim3(D / 32, DFF / 32), 256>>>(W2, pw2h, pw2l, DFF, D);

    // 1) LN1 -> x hi/lo
    ln_kernel<<<NT, 256>>>(embds, nullptr, ln1_g, ln1_b, pxh, pxl, nullptr);

    // 2) QKV -> bf16 hi/lo
    gemm_mma<false, false, false, true><<<dim3(NT / 128, QKVW / 128), 256>>>(
        pxh, pxl, pbqh, pbql, nullptr, nullptr, nullptr, pqvh, pqvl, D, D, D, QKVW);

    // 3) HMMA causal flash attention
    attn_mma<<<dim3(T / 64, Bb * H), 128, ATT_SM>>>(pqvh, pqvl, pattn);

    // 4) Residual + LN2 -> y hi/lo, x2 fp32
    ln_kernel<<<NT, 256>>>(embds, pattn, ln2_g, ln2_b, pyh, pyl, px2);

    // 5) FFN up -> h hi/lo
    gemm_mma<true, true, false, true><<<dim3(NT / 128, DFF / 128), 256>>>(
        pyh, pyl, pw1h, pw1l, b1, nullptr, nullptr, phh, phl, D, D, D, DFF);

    // 6) FFN down + bias + residual -> out fp32
    gemm_mma<false, true, true, false><<<dim3(NT / 128, D / 128), 256>>>(
        phh, phl, pw2h, pw2l, b2, px2, out, nullptr, nullptr, DFF, DFF, DFF, D);
}